// round 9
// baseline (speedup 1.0000x reference)
#include <cuda_runtime.h>

// ---------------- scratch (no allocs allowed) ----------------
__device__ float g_EsP[32][8][180];      // moment partials per (batch, m-tile)
__device__ float g_h1 [32 * 32 * 376];   // [b][co][lo], row padded 374->376
__device__ float g_h2 [32 * 64 * 96];    // [b][co][lo], row padded 92->96
__device__ unsigned g_bar = 0;           // monotonic grid barrier counter

#define NBLK 296
#define NTHR 256

// ---------------- f32x2 helpers ----------------
typedef unsigned long long ull;

__device__ __forceinline__ float2 unpack2(ull v) {
    float2 f; asm("mov.b64 {%0, %1}, %2;" : "=f"(f.x), "=f"(f.y) : "l"(v)); return f;
}
__device__ __forceinline__ ull ffma2(ull a, ull b, ull c) {
    ull d; asm("fma.rn.f32x2 %0, %1, %2, %3;" : "=l"(d) : "l"(a), "l"(b), "l"(c)); return d;
}

// grid-wide barrier, replay-safe (counter only grows; cohort = next multiple of NBLK)
__device__ __forceinline__ void grid_barrier() {
    __syncthreads();
    if (threadIdx.x == 0) {
        __threadfence();
        unsigned a = atomicAdd(&g_bar, 1u) + 1u;
        unsigned target = ((a - 1u) / NBLK + 1u) * NBLK;
        while (*(volatile unsigned*)&g_bar < target) { }
        __threadfence();
    }
    __syncthreads();
}

// ================= single persistent kernel =================
// A1 (256 blocks = b x 8 m-tiles of 188): moment partials, warp-parallel dots.
// AB (384 tasks): evaluate ctx window in smem + conv1 -> g_h1 (fused).
// C  (192 tasks): conv2 -> g_h2.
// D  (32 blocks): conv3 + linear -> out.
__global__ void __launch_bounds__(NTHR, 2) fused_kernel(
        const float* __restrict__ sig,
        const float* __restrict__ wq, const float* __restrict__ bq,
        const float* __restrict__ wk, const float* __restrict__ bk,
        const float* __restrict__ wv, const float* __restrict__ bv,
        const float* __restrict__ w1, const float* __restrict__ b1,
        const float* __restrict__ w2, const float* __restrict__ b2,
        const float* __restrict__ w3, const float* __restrict__ b3,
        const float* __restrict__ wl, const float* __restrict__ bl,
        float* __restrict__ out) {
    extern __shared__ float smbuf[];
    __shared__ float cw[96];    // [0:24)wq [24:48)wk [48:72)wv [72:80)bq [80:88)bk [88:96)bv
    __shared__ float Pm[16];
    __shared__ float flat[176];

    int tid  = threadIdx.x;
    int warp = tid >> 5;
    int lane = tid & 31;

    const float QS = 0.02581988897471611f;  // 1/sqrt(1500)
    const float C6 = 0.16666666666666666f;

    if (tid < 24)      cw[tid] = wq[tid];
    else if (tid < 48) cw[tid] = wk[tid - 24];
    else if (tid < 72) cw[tid] = wv[tid - 48];
    else if (tid < 80) cw[tid] = bq[tid - 72];
    else if (tid < 88) cw[tid] = bk[tid - 80];
    else if (tid < 96) cw[tid] = bv[tid - 88];
    __syncthreads();

    // ---------------- Phase A1: moment partials (blocks 0..255) ----------------
    if (blockIdx.x < 256) {
        const int b = blockIdx.x >> 3;
        const int T = blockIdx.x & 7;
        const int mbase = T * 188;
        const int len = (T == 7) ? 184 : 188;
        const float* sigb = sig + b * 1500;

        float* coef = smbuf;              // [20][192]
        float* vv   = smbuf + 20 * 192;   // [9][192], row 8 = ones

        // Pm[j][i] = QS * sum_c (j<3 ? wq[c*3+j] : bq[c]) * (i<3 ? wk[c*3+i] : bk[c])
        if (tid < 16) {
            int j = tid >> 2, i = tid & 3;
            float s = 0.f;
#pragma unroll
            for (int c = 0; c < 8; c++) {
                float qv = (j < 3) ? cw[c*3 + j] : cw[72 + c];
                float kv = (i < 3) ? cw[24 + c*3 + i] : cw[80 + c];
                s = fmaf(qv, kv, s);
            }
            Pm[tid] = s * QS;
        }
        __syncthreads();

        for (int j = tid; j < len; j += NTHR) {
            int m = mbase + j;
            float xm1 = (m > 0)    ? sigb[m - 1] : 0.f;
            float x0  = sigb[m];
            float xp1 = (m < 1499) ? sigb[m + 1] : 0.f;
            float a0 = fmaf(Pm[0],  xm1, fmaf(Pm[1],  x0, fmaf(Pm[2],  xp1, Pm[3])));
            float a1 = fmaf(Pm[4],  xm1, fmaf(Pm[5],  x0, fmaf(Pm[6],  xp1, Pm[7])));
            float a2 = fmaf(Pm[8],  xm1, fmaf(Pm[9],  x0, fmaf(Pm[10], xp1, Pm[11])));
            float a3 = fmaf(Pm[12], xm1, fmaf(Pm[13], x0, fmaf(Pm[14], xp1, Pm[15])));

            float p1 = fmaf(a3, fmaf(0.5f, a3, 1.f), 1.f);     // 1 + a3 + a3^2/2
            float p0 = fmaf(a3 * a3 * a3, C6, p1);             // + a3^3/6
            float p2 = fmaf(0.5f, a3, 0.5f);
            float q2 = a3 + 1.f;

            float a00 = a0*a0, a01 = a0*a1, a02 = a0*a2;
            float a11 = a1*a1, a12 = a1*a2, a22 = a2*a2;

            coef[ 0*192 + j] = p0;
            coef[ 1*192 + j] = p1 * a0;
            coef[ 2*192 + j] = p1 * a1;
            coef[ 3*192 + j] = p1 * a2;
            coef[ 4*192 + j] = p2 * a00;
            coef[ 5*192 + j] = q2 * a01;
            coef[ 6*192 + j] = q2 * a02;
            coef[ 7*192 + j] = p2 * a11;
            coef[ 8*192 + j] = q2 * a12;
            coef[ 9*192 + j] = p2 * a22;
            coef[10*192 + j] = C6  * a00 * a0;
            coef[11*192 + j] = 0.5f * a00 * a1;
            coef[12*192 + j] = 0.5f * a00 * a2;
            coef[13*192 + j] = 0.5f * a0  * a11;
            coef[14*192 + j] =        a01 * a2;
            coef[15*192 + j] = 0.5f * a0  * a22;
            coef[16*192 + j] = C6  * a11 * a1;
            coef[17*192 + j] = 0.5f * a11 * a2;
            coef[18*192 + j] = 0.5f * a1  * a22;
            coef[19*192 + j] = C6  * a22 * a2;
#pragma unroll
            for (int c = 0; c < 8; c++) {
                vv[c*192 + j] = fmaf(cw[48 + c*3], xm1,
                                 fmaf(cw[49 + c*3], x0,
                                 fmaf(cw[50 + c*3], xp1, cw[88 + c])));
            }
            vv[8*192 + j] = 1.f;
        }
        __syncthreads();

        // warp-parallel dot products: 180 pairs over 8 warps
        for (int pair = warp; pair < 180; pair += 8) {
            int t = pair / 9, c = pair % 9;
            const float* cp = coef + t * 192;
            const float* vp = vv   + c * 192;
            float s = 0.f;
            for (int j = lane; j < len; j += 32) s = fmaf(cp[j], vp[j], s);
#pragma unroll
            for (int off = 16; off; off >>= 1) s += __shfl_xor_sync(0xffffffffu, s, off);
            if (lane == 0) g_EsP[b][T][pair] = s;
        }
    }

    grid_barrier();   // g_EsP visible

    // ---------------- Phase AB: ctx eval + conv1 fused (384 tasks) ----------------
    {
        float* xs  = smbuf;           // [8][136] ctx window
        float* ws  = smbuf + 4352;    // 2048 floats (w1)
        float* esS = smbuf + 6400;    // [180]
        for (int i = tid; i < 2048; i += NTHR) ws[i] = w1[i];

        for (int task = blockIdx.x; task < 384; task += NBLK) {
            int b = task / 12, t = task % 12;
            const float* sigb = sig + b * 1500;

            __syncthreads();   // xs/esS reuse across tasks
            if (tid < 180) {
                float s = 0.f;
#pragma unroll
                for (int T = 0; T < 8; T++) s += g_EsP[b][T][tid];
                esS[tid] = s;
            }
            __syncthreads();

            // evaluate ctx columns l = 128t + j, j in [0,136), h = channel half
            for (int i = tid; i < 272; i += NTHR) {
                int h = (i < 136) ? 0 : 1;
                int j = i - h * 136;
                int cb = h * 4;
                int l = 128 * t + j;
                if (l < 1500) {
                    float y0 = (l > 0)    ? sigb[l - 1] : 0.f;
                    float y1 = sigb[l];
                    float y2 = (l < 1499) ? sigb[l + 1] : 0.f;
                    float u[20];
                    u[0] = 1.f;  u[1] = y0;  u[2] = y1;  u[3] = y2;
                    u[4] = y0*y0; u[5] = y0*y1; u[6] = y0*y2; u[7] = y1*y1; u[8] = y1*y2; u[9] = y2*y2;
                    u[10] = u[4]*y0; u[11] = u[4]*y1; u[12] = u[4]*y2; u[13] = y0*u[7]; u[14] = u[5]*y2;
                    u[15] = y0*u[9]; u[16] = u[7]*y1; u[17] = u[7]*y2; u[18] = y1*u[9]; u[19] = u[9]*y2;

                    float cx0 = 0.f, cx1 = 0.f, cx2 = 0.f, cx3 = 0.f, den = 0.f;
#pragma unroll
                    for (int tt = 0; tt < 20; tt++) {
                        float ut = u[tt];
                        den = fmaf(ut, esS[tt*9 + 8], den);
                        cx0 = fmaf(ut, esS[tt*9 + cb + 0], cx0);
                        cx1 = fmaf(ut, esS[tt*9 + cb + 1], cx1);
                        cx2 = fmaf(ut, esS[tt*9 + cb + 2], cx2);
                        cx3 = fmaf(ut, esS[tt*9 + cb + 3], cx3);
                    }
                    float inv = 1.f / den;
                    xs[(cb + 0) * 136 + j] = cx0 * inv;
                    xs[(cb + 1) * 136 + j] = cx1 * inv;
                    xs[(cb + 2) * 136 + j] = cx2 * inv;
                    xs[(cb + 3) * 136 + j] = cx3 * inv;
                } else {
                    xs[(cb + 0) * 136 + j] = 0.f;
                    xs[(cb + 1) * 136 + j] = 0.f;
                    xs[(cb + 2) * 136 + j] = 0.f;
                    xs[(cb + 3) * 136 + j] = 0.f;
                }
            }
            __syncthreads();

            // conv1: 8 warps, 4 co each, f32x2 over k-pairs
            {
                int lo  = t * 32 + lane;
                int cob = warp * 4;
                const ull* xsu = (const ull*)xs;   // per-ci: 68 ull
                const ull* wsu = (const ull*)ws;   // [co][ci][kpair]
                ull acc[4] = {0ull, 0ull, 0ull, 0ull};
#pragma unroll
                for (int ci = 0; ci < 8; ci++) {
                    ull x[4];
#pragma unroll
                    for (int kp = 0; kp < 4; kp++) x[kp] = xsu[ci * 68 + 2 * lane + kp];
#pragma unroll
                    for (int co = 0; co < 4; co++)
#pragma unroll
                        for (int kp = 0; kp < 4; kp++)
                            acc[co] = ffma2(wsu[(cob + co) * 32 + ci * 4 + kp], x[kp], acc[co]);
                }
                if (lo < 374) {
#pragma unroll
                    for (int co = 0; co < 4; co++) {
                        float2 f = unpack2(acc[co]);
                        g_h1[(b * 32 + cob + co) * 376 + lo] = f.x + f.y + b1[cob + co];
                    }
                }
            }
        }
    }

    grid_barrier();   // g_h1 visible

    // ---------------- Phase C: conv2 (32->64, k8 s4), 192 tasks ----------------
    {
        float* xs = smbuf;          // [32][136] = 4352 floats
        float* ws = smbuf + 4352;   // 8192 floats (half of w2)

        for (int task = blockIdx.x; task < 192; task += NBLK) {
            int b   = task / 6;
            int coh = (task / 3) % 2;
            int t   = task % 3;
            __syncthreads();
            const float4* w4 = (const float4*)(w2 + coh * 8192);
            float4* ws4 = (float4*)ws;
            for (int i = tid; i < 2048; i += NTHR) ws4[i] = w4[i];
            for (int i = tid; i < 4352; i += NTHR) {
                int ci = i / 136, j = i % 136;
                int gx = 128 * t + j;
                xs[i] = (gx < 374) ? g_h1[(b * 32 + ci) * 376 + gx] : 0.f;
            }
            __syncthreads();

            {
                int lo  = t * 32 + lane;
                int col = warp * 4;
                const ull* xsu = (const ull*)xs;
                const ull* wsu = (const ull*)ws;
                ull acc[4] = {0ull, 0ull, 0ull, 0ull};
                ull xa[4], xb[4];
#pragma unroll
                for (int kp = 0; kp < 4; kp++) xa[kp] = xsu[2 * lane + kp];
#pragma unroll
                for (int ci = 0; ci < 32; ci += 2) {
#pragma unroll
                    for (int kp = 0; kp < 4; kp++) xb[kp] = xsu[(ci + 1) * 68 + 2 * lane + kp];
#pragma unroll
                    for (int j = 0; j < 4; j++)
#pragma unroll
                        for (int kp = 0; kp < 4; kp++)
                            acc[j] = ffma2(wsu[(col + j) * 128 + ci * 4 + kp], xa[kp], acc[j]);
                    if (ci + 2 < 32) {
#pragma unroll
                        for (int kp = 0; kp < 4; kp++) xa[kp] = xsu[(ci + 2) * 68 + 2 * lane + kp];
                    }
#pragma unroll
                    for (int j = 0; j < 4; j++)
#pragma unroll
                        for (int kp = 0; kp < 4; kp++)
                            acc[j] = ffma2(wsu[(col + j) * 128 + (ci + 1) * 4 + kp], xb[kp], acc[j]);
                }
                if (lo < 92) {
                    int cog = coh * 32 + col;
#pragma unroll
                    for (int j = 0; j < 4; j++) {
                        float2 f = unpack2(acc[j]);
                        g_h2[(b * 64 + cog + j) * 96 + lo] = f.x + f.y + b2[cog + j];
                    }
                }
            }
        }
    }

    grid_barrier();   // g_h2 visible

    // ---------------- Phase D: conv3 (64->8) + linear ----------------
    if (blockIdx.x < 32) {
        int b = blockIdx.x;
        if (lane < 22) {
            float acc = b3[warp];
            const float* wp = w3 + warp * 512;
#pragma unroll 8
            for (int ci = 0; ci < 64; ci++) {
                const float4* xp = (const float4*)(g_h2 + (b * 64 + ci) * 96 + 4 * lane);
                float4 x0 = xp[0], x1 = xp[1];
                const float* w = wp + ci * 8;
                acc += w[0]*x0.x + w[1]*x0.y + w[2]*x0.z + w[3]*x0.w
                     + w[4]*x1.x + w[5]*x1.y + w[6]*x1.z + w[7]*x1.w;
            }
            flat[warp * 22 + lane] = acc;
        }
        __syncthreads();

        if (warp < 3) {
            float s = 0.f;
            for (int i = lane; i < 176; i += 32) s += wl[warp * 176 + i] * flat[i];
#pragma unroll
            for (int off = 16; off; off >>= 1) s += __shfl_xor_sync(0xffffffffu, s, off);
            if (lane == 0) out[b * 3 + warp] = s + bl[warp];
        }
    }
}

// ---------------- launch ----------------
extern "C" void kernel_launch(void* const* d_in, const int* in_sizes, int n_in,
                              void* d_out, int out_size) {
    const float* signal = (const float*)d_in[0];
    const float* wq = (const float*)d_in[1];
    const float* bq = (const float*)d_in[2];
    const float* wk = (const float*)d_in[3];
    const float* bk = (const float*)d_in[4];
    const float* wv = (const float*)d_in[5];
    const float* bv = (const float*)d_in[6];
    const float* w1 = (const float*)d_in[7];
    const float* b1 = (const float*)d_in[8];
    const float* w2 = (const float*)d_in[9];
    const float* b2 = (const float*)d_in[10];
    const float* w3 = (const float*)d_in[11];
    const float* b3 = (const float*)d_in[12];
    const float* wl = (const float*)d_in[13];
    const float* bl = (const float*)d_in[14];
    float* out = (float*)d_out;

    cudaFuncSetAttribute(fused_kernel, cudaFuncAttributeMaxDynamicSharedMemorySize, 50176);
    fused_kernel<<<NBLK, NTHR, 50176>>>(signal, wq, bq, wk, bk, wv, bv,
                                        w1, b1, w2, b2, w3, b3, wl, bl, out);
}